// round 6
// baseline (speedup 1.0000x reference)
#include <cuda_runtime.h>
#include <cstdint>

#define Bz  8
#define Sz  256
#define Hz  128
#define HDz 32
#define BSz 2048
#define SCALE 0.17677669529663687f   // 1/sqrt(32)
#define TST 136                       // 64-row tile stride: conflict-free for both phases
#define QK  64                        // keys per rel CTA (quarter)

// __device__ scratch (allocation-free rule)
__device__ float g_Q[BSz * Hz];
__device__ float g_Keff[BSz * Hz];
__device__ float g_Veff[BSz * Hz];
__device__ float g_sbase[Bz * 4 * Sz * Sz];     // [b][h][q][k]
__device__ float g_probs[Bz * 4 * Sz * Sz];     // abs: normalized; rel: pexp (scaled in ctxv)
__device__ float g_pscale[Bz * 4 * Sz * 4];     // per (b,h,q,quarter) prob scale
__device__ float g_mred[Bz * 2 * Sz * 4 * 2];   // (m,l) per (b,i,q,quarter)
__device__ float g_wpart[Bz * 2 * Sz * 4 * Hz]; // wacc per (b,i,q,quarter)[128]
__device__ float g_ctxbase[BSz * Hz];
__device__ float g_ctx[BSz * Hz];

#define CP_ASYNC16(dst, src) \
    asm volatile("cp.async.cg.shared.global [%0], [%1], 16;\n" :: "r"(dst), "l"(src))
#define CP_COMMIT() asm volatile("cp.async.commit_group;\n" ::: "memory")
#define CP_WAIT0()  asm volatile("cp.async.wait_group 0;\n" ::: "memory")

// ---------------------------------------------------------------------------
// K0: projections. 2 rows per CTA, 128 threads.
// ---------------------------------------------------------------------------
__global__ void proj_kernel(const float* __restrict__ X,
                            const float* __restrict__ abs0,
                            const float* __restrict__ abs1,
                            const float* __restrict__ Wq, const float* __restrict__ bq,
                            const float* __restrict__ Wk, const float* __restrict__ bk,
                            const float* __restrict__ Wv, const float* __restrict__ bv) {
    int r0 = blockIdx.x * 2;
    int j  = threadIdx.x;
    __shared__ float xs[2][Hz], a0s[2][Hz], a1s[2][Hz];
    #pragma unroll
    for (int r = 0; r < 2; r++) {
        xs[r][j]  = X[(r0 + r) * Hz + j];
        a0s[r][j] = abs0[(r0 + r) * Hz + j];
        a1s[r][j] = abs1[(r0 + r) * Hz + j];
    }
    __syncthreads();

    float q0 = bq[j], k0 = bk[j], v0 = bv[j];
    float q1 = q0, k1 = k0, v1 = v0;
    #pragma unroll 4
    for (int i = 0; i < Hz; i++) {
        float wq = Wq[i * Hz + j], wk = Wk[i * Hz + j], wv = Wv[i * Hz + j];
        float x0 = xs[0][i], x1 = xs[1][i];
        q0 += x0 * wq; k0 += x0 * wk; v0 += x0 * wv;
        q1 += x1 * wq; k1 += x1 * wk; v1 += x1 * wv;
    }
    if (j < 64) {   // abs-head folds
        float ka0 = bk[j], va0 = bv[j], ka1 = ka0, va1 = va0;
        #pragma unroll 4
        for (int i = 0; i < Hz; i++) {
            float wk = Wk[i * Hz + j], wv = Wv[i * Hz + j];
            float b0 = (j < 32) ? a0s[0][i] : a1s[0][i];
            float b1 = (j < 32) ? a0s[1][i] : a1s[1][i];
            ka0 += b0 * wk; va0 += b0 * wv;
            ka1 += b1 * wk; va1 += b1 * wv;
        }
        k0 += ka0; v0 += va0; k1 += ka1; v1 += va1;
    }
    g_Q[r0 * Hz + j] = q0;        g_Q[(r0 + 1) * Hz + j] = q1;
    g_Keff[r0 * Hz + j] = k0;     g_Keff[(r0 + 1) * Hz + j] = k1;
    g_Veff[r0 * Hz + j] = v0;     g_Veff[(r0 + 1) * Hz + j] = v1;
}

// ---------------------------------------------------------------------------
// K1: sbase[b,h,q,k] = (Q_h[q].Keff_h[k])*SCALE + mask[b,q,k]
// ---------------------------------------------------------------------------
__global__ void __launch_bounds__(256) sbase_kernel(const float* __restrict__ mask) {
    int qt = blockIdx.x, b = blockIdx.y, h = blockIdx.z;
    int t = threadIdx.x;
    __shared__ float Qs[32 * 32];
    __shared__ float ks[256 * 33];

    #pragma unroll
    for (int r = 0; r < 4; r++) {
        int idx = r * 256 + t;
        int qq = idx >> 5, c = idx & 31;
        Qs[idx] = g_Q[(b * Sz + qt * 32 + qq) * Hz + h * HDz + c];
    }
    #pragma unroll
    for (int jj = 0; jj < 8; jj++) {
        int idx = jj * 256 + t;
        int row = idx >> 3, c4 = idx & 7;
        float4 v = *(const float4*)&g_Keff[(b * Sz + row) * Hz + h * HDz + c4 * 4];
        ks[row * 33 + c4 * 4 + 0] = v.x;
        ks[row * 33 + c4 * 4 + 1] = v.y;
        ks[row * 33 + c4 * 4 + 2] = v.z;
        ks[row * 33 + c4 * 4 + 3] = v.w;
    }
    __syncthreads();

    float kr[32];
    #pragma unroll
    for (int c = 0; c < 32; c++) kr[c] = ks[t * 33 + c];

    int qbase = qt * 32;
    #pragma unroll 2
    for (int qq = 0; qq < 32; qq++) {
        float acc = 0.f;
        #pragma unroll
        for (int c = 0; c < 32; c++) acc += Qs[qq * 32 + c] * kr[c];
        int q = qbase + qq;
        g_sbase[((b * 4 + h) * Sz + q) * Sz + t] =
            acc * SCALE + mask[(b * Sz + q) * Sz + t];
    }
}

// ---------------------------------------------------------------------------
// K2: rel split-K (quarters). CTA per (q, b, i*4+quarter); 128 threads.
// Warp w owns local keys 16w..16w+15 (2 threads/key). 32KB tile, 6 CTAs/SM.
// Outputs per quarter: pexp (unnormalized), (m,l), wacc[128].
// ---------------------------------------------------------------------------
__global__ void __launch_bounds__(128, 6) rel_kernel(
        const float* __restrict__ rel0, const float* __restrict__ rel1,
        const float* __restrict__ Wk) {
    int q = blockIdx.x, b = blockIdx.y;
    int i = blockIdx.z >> 2, quarter = blockIdx.z & 3;
    int hr = 2 + i;
    int kbase = quarter * QK;
    int t = threadIdx.x, lane = t & 31, w = t >> 5;

    extern __shared__ float sm[];
    float* tile = sm;                 // [QK][TST]
    float* uvec = sm + QK * TST;      // 128
    float* kb   = uvec + 128;         // 64
    float* pc   = kb + 64;            // 64
    float* qvr  = pc + 64;            // 32
    float* wm   = qvr + 32;           // 4
    float* wl   = wm + 4;             // 4

    // 1) issue all loads (warp w loads rows 16w..16w+15; lane = float4 column)
    const float4* rp4 = (const float4*)(((i == 0) ? rel0 : rel1)
                        + (size_t)(b * Sz + q) * Sz * Hz) + (size_t)kbase * 32;
    uint32_t tileu = (uint32_t)__cvta_generic_to_shared(tile);
    #pragma unroll
    for (int r = 0; r < 16; r++) {
        int row = w * 16 + r;
        uint32_t d = tileu + (uint32_t)(row * TST + lane * 4) * 4;
        CP_ASYNC16(d, rp4 + row * 32 + lane);
    }
    CP_COMMIT();

    // 2) prologue (overlaps DRAM)
    if (t < 32) qvr[t] = g_Q[(b * Sz + q) * Hz + hr * HDz + t];
    if (t < QK) kb[t] = g_sbase[((b * 4 + hr) * Sz + q) * Sz + kbase + t];
    __syncthreads();

    // 3) u = Wk_hr^T q_hr
    {
        float acc = 0.f;
        const float* wrow = Wk + t * Hz + hr * HDz;
        #pragma unroll
        for (int c = 0; c < HDz; c++) acc += wrow[c] * qvr[c];
        uvec[t] = acc;
    }
    __syncthreads();

    // 4) per-warp wait + score. key = t>>1, part = t&1 (channels part*4 + 8j..)
    CP_WAIT0();
    __syncwarp();
    int key = t >> 1, part = t & 1;
    float s;
    {
        const float* row = &tile[key * TST + part * 4];
        const float* up  = &uvec[part * 4];
        float acc = 0.f;
        #pragma unroll
        for (int j = 0; j < 16; j++) {
            float4 r = *(const float4*)&row[j * 8];
            float4 u = *(const float4*)&up[j * 8];
            acc += r.x * u.x + r.y * u.y + r.z * u.z + r.w * u.w;
        }
        acc += __shfl_xor_sync(~0u, acc, 1);     // merge the two parts
        s = acc * SCALE + kb[key];
    }
    float mw = s;
    #pragma unroll
    for (int o = 16; o; o >>= 1) mw = fmaxf(mw, __shfl_xor_sync(~0u, mw, o));
    if (lane == 0) wm[w] = mw;
    __syncthreads();

    // 5) quarter-local max, p, quarter-local sum
    float M = fmaxf(fmaxf(wm[0], wm[1]), fmaxf(wm[2], wm[3]));
    float p = __expf(s - M);
    if (part == 0) pc[key] = p;
    float lw = (part == 0) ? p : 0.f;
    #pragma unroll
    for (int o = 16; o; o >>= 1) lw += __shfl_xor_sync(~0u, lw, o);
    if (lane == 0) wl[w] = lw;
    __syncthreads();
    float L = wl[0] + wl[1] + wl[2] + wl[3];

    if (t < QK)
        g_probs[((b * 4 + hr) * Sz + q) * Sz + kbase + t] = pc[t];
    if (t == 0) {
        int mi = ((b * 2 + i) * Sz + q) * 4 + quarter;
        g_mred[mi * 2 + 0] = M;
        g_mred[mi * 2 + 1] = L;
    }

    // 6) wacc[ch] = sum_k pc[k] * tile[k][ch]  (thread = channel)
    {
        float wacc = 0.f;
        #pragma unroll 8
        for (int k = 0; k < QK; k++)
            wacc += pc[k] * tile[k * TST + t];
        g_wpart[(((b * 2 + i) * Sz + q) * 4 + quarter) * Hz + t] = wacc;
    }
}

// ---------------------------------------------------------------------------
// K2b: combine. CTA per (q, b, i); 128 threads. Merges 4 quarters,
// projects w through Wv_hr -> ctxbase, writes pscale, abs softmax.
// ---------------------------------------------------------------------------
__global__ void __launch_bounds__(128) combine_kernel(
        const float* __restrict__ Wv, const float* __restrict__ bv) {
    int q = blockIdx.x, b = blockIdx.y, i = blockIdx.z;
    int hr = 2 + i, ha = i;
    int t = threadIdx.x, lane = t & 31, w = t >> 5;

    __shared__ float wfin[Hz];
    __shared__ float wp2[Hz];
    __shared__ float red[4];
    __shared__ float sc2[4];

    int mi = ((b * 2 + i) * Sz + q) * 4;
    float mv0 = g_mred[(mi + 0) * 2], lv0 = g_mred[(mi + 0) * 2 + 1];
    float mv1 = g_mred[(mi + 1) * 2], lv1 = g_mred[(mi + 1) * 2 + 1];
    float mv2 = g_mred[(mi + 2) * 2], lv2 = g_mred[(mi + 2) * 2 + 1];
    float mv3 = g_mred[(mi + 3) * 2], lv3 = g_mred[(mi + 3) * 2 + 1];
    float M = fmaxf(fmaxf(mv0, mv1), fmaxf(mv2, mv3));
    float c0 = __expf(mv0 - M), c1 = __expf(mv1 - M);
    float c2 = __expf(mv2 - M), c3 = __expf(mv3 - M);
    float invL = 1.f / (lv0 * c0 + lv1 * c1 + lv2 * c2 + lv3 * c3);

    wfin[t] = g_wpart[(mi + 0) * Hz + t] * c0 + g_wpart[(mi + 1) * Hz + t] * c1
            + g_wpart[(mi + 2) * Hz + t] * c2 + g_wpart[(mi + 3) * Hz + t] * c3;

    if (t < 4) {
        float c = (t == 0) ? c0 : (t == 1) ? c1 : (t == 2) ? c2 : c3;
        g_pscale[((b * 4 + hr) * Sz + q) * 4 + t] = c * invL;
        g_pscale[((b * 4 + ha) * Sz + q) * 4 + t] = 1.f;
    }

    // abs-head softmax over 256 (2 values per thread)
    float sa0 = g_sbase[((b * 4 + ha) * Sz + q) * Sz + t];
    float sa1 = g_sbase[((b * 4 + ha) * Sz + q) * Sz + t + 128];
    float mv = fmaxf(sa0, sa1);
    #pragma unroll
    for (int o = 16; o; o >>= 1) mv = fmaxf(mv, __shfl_xor_sync(~0u, mv, o));
    if (lane == 0) red[w] = mv;
    __syncthreads();
    float Ma = fmaxf(fmaxf(red[0], red[1]), fmaxf(red[2], red[3]));
    float p0 = __expf(sa0 - Ma), p1 = __expf(sa1 - Ma);
    float sv = p0 + p1;
    #pragma unroll
    for (int o = 16; o; o >>= 1) sv += __shfl_xor_sync(~0u, sv, o);
    if (lane == 0) sc2[w] = sv;
    __syncthreads();
    float invLa = 1.f / (sc2[0] + sc2[1] + sc2[2] + sc2[3]);
    g_probs[((b * 4 + ha) * Sz + q) * Sz + t]       = p0 * invLa;
    g_probs[((b * 4 + ha) * Sz + q) * Sz + t + 128] = p1 * invLa;
    if (t < HDz) g_ctxbase[(b * Sz + q) * Hz + ha * HDz + t] = 0.f;

    // project wfin through Wv_hr (4 groups of 32 channels)
    {
        int c = t & 31, g = t >> 5;
        float pp = 0.f;
        #pragma unroll
        for (int j = 0; j < 32; j++)
            pp += wfin[g * 32 + j] * Wv[(g * 32 + j) * Hz + hr * HDz + c];
        wp2[t] = pp;
    }
    __syncthreads();
    if (t < HDz) {
        float ww = wp2[t] + wp2[t + 32] + wp2[t + 64] + wp2[t + 96];
        g_ctxbase[(b * Sz + q) * Hz + hr * HDz + t] = ww * invL + bv[hr * HDz + t];
    }
}

// ---------------------------------------------------------------------------
// K3: ctx = ctxbase + probs(scaled) @ Veff. grid (8,8,4), 256 threads.
// ---------------------------------------------------------------------------
__global__ void __launch_bounds__(256) ctxv_kernel() {
    int qt = blockIdx.x, b = blockIdx.y, h = blockIdx.z;
    int t = threadIdx.x;
    extern __shared__ float sm3[];
    float* Vs  = sm3;                        // 256*33
    float* Ps  = sm3 + 256 * 33;             // 32*256
    float* psc = sm3 + 256 * 33 + 32 * 256;  // 128

    if (t < 128)
        psc[t] = g_pscale[((b * 4 + h) * Sz + qt * 32 + (t >> 2)) * 4 + (t & 3)];
    #pragma unroll
    for (int jj = 0; jj < 8; jj++) {
        int idx = jj * 256 + t;
        int row = idx >> 3, c4 = idx & 7;
        float4 v = *(const float4*)&g_Veff[(b * Sz + row) * Hz + h * HDz + c4 * 4];
        Vs[row * 33 + c4 * 4 + 0] = v.x;
        Vs[row * 33 + c4 * 4 + 1] = v.y;
        Vs[row * 33 + c4 * 4 + 2] = v.z;
        Vs[row * 33 + c4 * 4 + 3] = v.w;
    }
    __syncthreads();
    #pragma unroll
    for (int jj = 0; jj < 8; jj++) {
        int idx = jj * 256 + t;
        int qq = idx >> 6, k4 = idx & 63;
        float4 v = *(const float4*)&g_probs[((b * 4 + h) * Sz + qt * 32 + qq) * Sz + k4 * 4];
        float sc = psc[qq * 4 + (k4 >> 4)];
        v.x *= sc; v.y *= sc; v.z *= sc; v.w *= sc;
        *(float4*)&Ps[qq * 256 + k4 * 4] = v;
    }
    __syncthreads();

    int c = t & 31, q0 = t >> 5;
    const float4* Ps4 = (const float4*)Ps;
    float acc0 = 0.f, acc1 = 0.f, acc2 = 0.f, acc3 = 0.f;
    #pragma unroll 4
    for (int k4 = 0; k4 < 64; k4++) {
        float v0 = Vs[(k4 * 4 + 0) * 33 + c];
        float v1 = Vs[(k4 * 4 + 1) * 33 + c];
        float v2 = Vs[(k4 * 4 + 2) * 33 + c];
        float v3 = Vs[(k4 * 4 + 3) * 33 + c];
        float4 P0 = Ps4[(q0     ) * 64 + k4];
        float4 P1 = Ps4[(q0 +  8) * 64 + k4];
        float4 P2 = Ps4[(q0 + 16) * 64 + k4];
        float4 P3 = Ps4[(q0 + 24) * 64 + k4];
        acc0 += P0.x * v0 + P0.y * v1 + P0.z * v2 + P0.w * v3;
        acc1 += P1.x * v0 + P1.y * v1 + P1.z * v2 + P1.w * v3;
        acc2 += P2.x * v0 + P2.y * v1 + P2.z * v2 + P2.w * v3;
        acc3 += P3.x * v0 + P3.y * v1 + P3.z * v2 + P3.w * v3;
    }
    #pragma unroll
    for (int r = 0; r < 4; r++) {
        int q = qt * 32 + q0 + r * 8;
        float a = (r == 0) ? acc0 : (r == 1) ? acc1 : (r == 2) ? acc2 : acc3;
        g_ctx[(b * Sz + q) * Hz + h * HDz + c] =
            g_ctxbase[(b * Sz + q) * Hz + h * HDz + c] + a;
    }
}

// ---------------------------------------------------------------------------
// K4: out = ctx @ Wo + bo. 4 rows per CTA.
// ---------------------------------------------------------------------------
__global__ void out_kernel(const float* __restrict__ Wo,
                           const float* __restrict__ bo,
                           float* __restrict__ out) {
    int r0 = blockIdx.x * 4;
    int j = threadIdx.x;
    __shared__ float xs[4][Hz];
    #pragma unroll
    for (int r = 0; r < 4; r++) xs[r][j] = g_ctx[(r0 + r) * Hz + j];
    __syncthreads();
    float a0 = bo[j], a1 = a0, a2 = a0, a3 = a0;
    #pragma unroll 4
    for (int i = 0; i < Hz; i++) {
        float w = Wo[i * Hz + j];
        a0 += xs[0][i] * w; a1 += xs[1][i] * w;
        a2 += xs[2][i] * w; a3 += xs[3][i] * w;
    }
    out[r0 * Hz + j] = a0;
    out[(r0 + 1) * Hz + j] = a1;
    out[(r0 + 2) * Hz + j] = a2;
    out[(r0 + 3) * Hz + j] = a3;
}

// ---------------------------------------------------------------------------
extern "C" void kernel_launch(void* const* d_in, const int* in_sizes, int n_in,
                              void* d_out, int out_size) {
    const float* X    = (const float*)d_in[0];
    const float* mask = (const float*)d_in[1];
    const float* abs0 = (const float*)d_in[2];
    const float* abs1 = (const float*)d_in[3];
    const float* rel0 = (const float*)d_in[4];
    const float* rel1 = (const float*)d_in[5];
    const float* Wq   = (const float*)d_in[6];
    const float* bq   = (const float*)d_in[7];
    const float* Wk   = (const float*)d_in[8];
    const float* bk   = (const float*)d_in[9];
    const float* Wv   = (const float*)d_in[10];
    const float* bv   = (const float*)d_in[11];
    const float* Wo   = (const float*)d_in[12];
    const float* bo   = (const float*)d_in[13];
    float* out = (float*)d_out;

    size_t relsm = (size_t)(QK * TST + 128 + 64 + 64 + 32 + 4 + 4) * sizeof(float);
    size_t ctxsm = (size_t)(256 * 33 + 32 * 256 + 128) * sizeof(float);
    cudaFuncSetAttribute(rel_kernel,  cudaFuncAttributeMaxDynamicSharedMemorySize, (int)relsm);
    cudaFuncSetAttribute(ctxv_kernel, cudaFuncAttributeMaxDynamicSharedMemorySize, (int)ctxsm);

    proj_kernel<<<BSz / 2, Hz>>>(X, abs0, abs1, Wq, bq, Wk, bk, Wv, bv);
    dim3 gs(8, Bz, 4);
    sbase_kernel<<<gs, 256>>>(mask);
    dim3 gr(Sz, Bz, 8);             // z = i*4 + quarter
    rel_kernel<<<gr, 128, relsm>>>(rel0, rel1, Wk);
    dim3 gc(Sz, Bz, 2);
    combine_kernel<<<gc, 128>>>(Wv, bv);
    ctxv_kernel<<<gs, 256, ctxsm>>>();
    out_kernel<<<BSz / 4, Hz>>>(Wo, bo, out);
}

// round 7
// speedup vs baseline: 2.0141x; 2.0141x over previous
#include <cuda_runtime.h>
#include <cstdint>

#define Bz  8
#define Sz  256
#define Hz  128
#define HDz 32
#define BSz 2048
#define SCALE 0.17677669529663687f   // 1/sqrt(32)
#define TST 132                       // tile row stride (floats): conflict-free both phases

// __device__ scratch (allocation-free rule)
__device__ float g_Q[BSz * Hz];
__device__ float g_Keff[BSz * Hz];
__device__ float g_Veff[BSz * Hz];
__device__ float g_u[Bz * 2 * Sz * Hz];        // u[b,i,q][128]
__device__ float g_sbase[Bz * 4 * Sz * Sz];    // [b][h][q][k]
__device__ float g_probs[Bz * 4 * Sz * Sz];    // abs: normalized; rel: pexp (scaled in ctxv)
__device__ float g_pscale[Bz * 4 * Sz * 2];    // per (b,h,q,half) prob scale
__device__ float g_mred[Bz * 2 * Sz * 2 * 2];  // (m,l) per (b,i,q,half)
__device__ float g_wpart[Bz * 2 * Sz * 2 * Hz];// wacc per (b,i,q,half)[128]
__device__ float g_ctxbase[BSz * Hz];
__device__ float g_ctx[BSz * Hz];

#define CP_ASYNC16(dst, src) \
    asm volatile("cp.async.cg.shared.global [%0], [%1], 16;\n" :: "r"(dst), "l"(src))
#define CP_COMMIT() asm volatile("cp.async.commit_group;\n" ::: "memory")
#define CP_WAIT0()  asm volatile("cp.async.wait_group 0;\n" ::: "memory")

// ---------------------------------------------------------------------------
// K0: projections. 2 rows per CTA, 128 threads.
// ---------------------------------------------------------------------------
__global__ void proj_kernel(const float* __restrict__ X,
                            const float* __restrict__ abs0,
                            const float* __restrict__ abs1,
                            const float* __restrict__ Wq, const float* __restrict__ bq,
                            const float* __restrict__ Wk, const float* __restrict__ bk,
                            const float* __restrict__ Wv, const float* __restrict__ bv) {
    int r0 = blockIdx.x * 2;
    int j  = threadIdx.x;
    __shared__ float xs[2][Hz], a0s[2][Hz], a1s[2][Hz];
    #pragma unroll
    for (int r = 0; r < 2; r++) {
        xs[r][j]  = X[(r0 + r) * Hz + j];
        a0s[r][j] = abs0[(r0 + r) * Hz + j];
        a1s[r][j] = abs1[(r0 + r) * Hz + j];
    }
    __syncthreads();

    float q0 = bq[j], k0 = bk[j], v0 = bv[j];
    float q1 = q0, k1 = k0, v1 = v0;
    #pragma unroll 4
    for (int i = 0; i < Hz; i++) {
        float wq = Wq[i * Hz + j], wk = Wk[i * Hz + j], wv = Wv[i * Hz + j];
        float x0 = xs[0][i], x1 = xs[1][i];
        q0 += x0 * wq; k0 += x0 * wk; v0 += x0 * wv;
        q1 += x1 * wq; k1 += x1 * wk; v1 += x1 * wv;
    }
    if (j < 64) {   // abs-head folds
        float ka0 = bk[j], va0 = bv[j], ka1 = ka0, va1 = va0;
        #pragma unroll 4
        for (int i = 0; i < Hz; i++) {
            float wk = Wk[i * Hz + j], wv = Wv[i * Hz + j];
            float b0 = (j < 32) ? a0s[0][i] : a1s[0][i];
            float b1 = (j < 32) ? a0s[1][i] : a1s[1][i];
            ka0 += b0 * wk; va0 += b0 * wv;
            ka1 += b1 * wk; va1 += b1 * wv;
        }
        k0 += ka0; v0 += va0; k1 += ka1; v1 += va1;
    }
    g_Q[r0 * Hz + j] = q0;        g_Q[(r0 + 1) * Hz + j] = q1;
    g_Keff[r0 * Hz + j] = k0;     g_Keff[(r0 + 1) * Hz + j] = k1;
    g_Veff[r0 * Hz + j] = v0;     g_Veff[(r0 + 1) * Hz + j] = v1;
}

// ---------------------------------------------------------------------------
// K1: sbase[b,h,q,k] = (Q_h[q].Keff_h[k])*SCALE + mask[b,q,k]
// ---------------------------------------------------------------------------
__global__ void __launch_bounds__(256) sbase_kernel(const float* __restrict__ mask) {
    int qt = blockIdx.x, b = blockIdx.y, h = blockIdx.z;
    int t = threadIdx.x;
    __shared__ float Qs[32 * 32];
    __shared__ float ks[256 * 33];

    #pragma unroll
    for (int r = 0; r < 4; r++) {
        int idx = r * 256 + t;
        int qq = idx >> 5, c = idx & 31;
        Qs[idx] = g_Q[(b * Sz + qt * 32 + qq) * Hz + h * HDz + c];
    }
    #pragma unroll
    for (int jj = 0; jj < 8; jj++) {
        int idx = jj * 256 + t;
        int row = idx >> 3, c4 = idx & 7;
        float4 v = *(const float4*)&g_Keff[(b * Sz + row) * Hz + h * HDz + c4 * 4];
        ks[row * 33 + c4 * 4 + 0] = v.x;
        ks[row * 33 + c4 * 4 + 1] = v.y;
        ks[row * 33 + c4 * 4 + 2] = v.z;
        ks[row * 33 + c4 * 4 + 3] = v.w;
    }
    __syncthreads();

    float kr[32];
    #pragma unroll
    for (int c = 0; c < 32; c++) kr[c] = ks[t * 33 + c];

    int qbase = qt * 32;
    #pragma unroll 2
    for (int qq = 0; qq < 32; qq++) {
        float acc = 0.f;
        #pragma unroll
        for (int c = 0; c < 32; c++) acc += Qs[qq * 32 + c] * kr[c];
        int q = qbase + qq;
        g_sbase[((b * 4 + h) * Sz + q) * Sz + t] =
            acc * SCALE + mask[(b * Sz + q) * Sz + t];
    }
}

// ---------------------------------------------------------------------------
// K1b: u[b,i,q,j] = sum_c Wk[j, hr*32+c] * Q[b,q,hr*32+c]
// grid (qt=8, b=8, i=2), 128 threads (thread = j).
// ---------------------------------------------------------------------------
__global__ void __launch_bounds__(128) u_kernel(const float* __restrict__ Wk) {
    int qt = blockIdx.x, b = blockIdx.y, i = blockIdx.z;
    int hr = 2 + i;
    int j = threadIdx.x;
    __shared__ float Qs[32][32];

    #pragma unroll
    for (int r = 0; r < 8; r++) {
        int idx = r * 128 + j;
        int qq = idx >> 5, c = idx & 31;
        Qs[qq][c] = g_Q[(b * Sz + qt * 32 + qq) * Hz + hr * HDz + c];
    }
    __syncthreads();

    float wr[32];
    #pragma unroll
    for (int c = 0; c < 32; c++) wr[c] = Wk[j * Hz + hr * HDz + c];

    #pragma unroll 4
    for (int qq = 0; qq < 32; qq++) {
        float acc = 0.f;
        #pragma unroll
        for (int c = 0; c < 32; c++) acc += wr[c] * Qs[qq][c];
        g_u[((b * 2 + i) * Sz + qt * 32 + qq) * Hz + j] = acc;
    }
}

// ---------------------------------------------------------------------------
// K2: rel split-K (halves). CTA per (q, b, i*2+half); 128 threads (4 warps).
// Warp w owns local keys 32w..32w+31 (lane = one key). All 64KB issued
// upfront; per-warp cp.async wait; scores in registers.
// Outputs per half: pexp (unnormalized), (m,l), wacc[128].
// ---------------------------------------------------------------------------
__global__ void __launch_bounds__(128, 3) rel_kernel(
        const float* __restrict__ rel0, const float* __restrict__ rel1) {
    int q = blockIdx.x, b = blockIdx.y;
    int i = blockIdx.z >> 1, half = blockIdx.z & 1;
    int hr = 2 + i;
    int kbase = half * 128;
    int t = threadIdx.x, lane = t & 31, w = t >> 5;

    extern __shared__ float sm[];
    float* tile = sm;                 // [128][TST]
    float* uvec = sm + 128 * TST;     // 128
    float* kb   = uvec + 128;         // 128
    float* pc   = kb + 128;           // 128
    float* wm   = pc + 128;           // 4
    float* wl   = wm + 4;             // 4

    // 1) issue ALL loads (per-warp rows; lane = float4 column)
    const float4* rp4 = (const float4*)(((i == 0) ? rel0 : rel1)
                        + (size_t)(b * Sz + q) * Sz * Hz) + (size_t)kbase * 32;
    uint32_t tileu = (uint32_t)__cvta_generic_to_shared(tile);
    #pragma unroll
    for (int r = 0; r < 32; r++) {
        int row = w * 32 + r;
        uint32_t d = tileu + (uint32_t)(row * TST + lane * 4) * 4;
        CP_ASYNC16(d, rp4 + row * 32 + lane);
    }
    CP_COMMIT();

    // 2) prologue loads (overlap DRAM): u + sbase row (both coalesced)
    uvec[t] = g_u[((b * 2 + i) * Sz + q) * Hz + t];
    kb[t]   = g_sbase[((b * 4 + hr) * Sz + q) * Sz + kbase + t];
    __syncthreads();

    // 3) per-warp: wait own rows, compute own 32 scores (row = key = t)
    CP_WAIT0();
    __syncwarp();
    float s;
    {
        const float4* row = (const float4*)&tile[t * TST];
        const float4* u4  = (const float4*)uvec;
        float acc = 0.f;
        #pragma unroll
        for (int j = 0; j < 32; j++) {
            float4 r = row[j], u = u4[j];
            acc += r.x * u.x + r.y * u.y + r.z * u.z + r.w * u.w;
        }
        s = acc * SCALE + kb[t];
    }
    float mw = s;
    #pragma unroll
    for (int o = 16; o; o >>= 1) mw = fmaxf(mw, __shfl_xor_sync(~0u, mw, o));
    if (lane == 0) wm[w] = mw;
    __syncthreads();

    // 4) half-local max, p, half-local sum
    float M = fmaxf(fmaxf(wm[0], wm[1]), fmaxf(wm[2], wm[3]));
    float p = __expf(s - M);
    pc[t] = p;
    float lw = p;
    #pragma unroll
    for (int o = 16; o; o >>= 1) lw += __shfl_xor_sync(~0u, lw, o);
    if (lane == 0) wl[w] = lw;
    __syncthreads();
    float L = wl[0] + wl[1] + wl[2] + wl[3];

    // store pexp (unnormalized wrt this half's M)
    g_probs[((b * 4 + hr) * Sz + q) * Sz + kbase + t] = p;
    if (t == 0) {
        int mi = ((b * 2 + i) * Sz + q) * 2 + half;
        g_mred[mi * 2 + 0] = M;
        g_mred[mi * 2 + 1] = L;
    }

    // 5) wacc[ch] = sum_k pc[k] * tile[k][ch]
    {
        float wacc = 0.f;
        #pragma unroll 8
        for (int k = 0; k < 128; k++)
            wacc += pc[k] * tile[k * TST + t];
        g_wpart[(((b * 2 + i) * Sz + q) * 2 + half) * Hz + t] = wacc;
    }
}

// ---------------------------------------------------------------------------
// K2b: combine. CTA per (q, b, i); 128 threads.
// Merges split-K halves (m,l,wacc), projects w through Wv_hr -> ctxbase,
// writes pscale for both heads, and does the abs-head softmax.
// ---------------------------------------------------------------------------
__global__ void __launch_bounds__(128) combine_kernel(
        const float* __restrict__ Wv, const float* __restrict__ bv) {
    int q = blockIdx.x, b = blockIdx.y, i = blockIdx.z;
    int hr = 2 + i, ha = i;
    int t = threadIdx.x, lane = t & 31, w = t >> 5;

    __shared__ float wfin[Hz];
    __shared__ float wp2[Hz];
    __shared__ float red[4];
    __shared__ float sc2[4];

    int mi = ((b * 2 + i) * Sz + q) * 2;
    float m0 = g_mred[(mi + 0) * 2 + 0], l0 = g_mred[(mi + 0) * 2 + 1];
    float m1 = g_mred[(mi + 1) * 2 + 0], l1 = g_mred[(mi + 1) * 2 + 1];
    float M = fmaxf(m0, m1);
    float c0 = __expf(m0 - M), c1 = __expf(m1 - M);
    float invL = 1.f / (l0 * c0 + l1 * c1);

    wfin[t] = g_wpart[(mi + 0) * Hz + t] * c0 + g_wpart[(mi + 1) * Hz + t] * c1;

    if (t == 0) {
        g_pscale[((b * 4 + hr) * Sz + q) * 2 + 0] = c0 * invL;
        g_pscale[((b * 4 + hr) * Sz + q) * 2 + 1] = c1 * invL;
        g_pscale[((b * 4 + ha) * Sz + q) * 2 + 0] = 1.f;
        g_pscale[((b * 4 + ha) * Sz + q) * 2 + 1] = 1.f;
    }

    // abs-head softmax over 256 (2 values per thread)
    float sa0 = g_sbase[((b * 4 + ha) * Sz + q) * Sz + t];
    float sa1 = g_sbase[((b * 4 + ha) * Sz + q) * Sz + t + 128];
    float mv = fmaxf(sa0, sa1);
    #pragma unroll
    for (int o = 16; o; o >>= 1) mv = fmaxf(mv, __shfl_xor_sync(~0u, mv, o));
    if (lane == 0) red[w] = mv;
    __syncthreads();
    float Ma = fmaxf(fmaxf(red[0], red[1]), fmaxf(red[2], red[3]));
    float p0 = __expf(sa0 - Ma), p1 = __expf(sa1 - Ma);
    float sv = p0 + p1;
    #pragma unroll
    for (int o = 16; o; o >>= 1) sv += __shfl_xor_sync(~0u, sv, o);
    if (lane == 0) sc2[w] = sv;
    __syncthreads();
    float invLa = 1.f / (sc2[0] + sc2[1] + sc2[2] + sc2[3]);
    g_probs[((b * 4 + ha) * Sz + q) * Sz + t]       = p0 * invLa;
    g_probs[((b * 4 + ha) * Sz + q) * Sz + t + 128] = p1 * invLa;
    if (t < HDz) g_ctxbase[(b * Sz + q) * Hz + ha * HDz + t] = 0.f;

    // project wfin through Wv_hr (4 groups of 32 channels)
    {
        int c = t & 31, g = t >> 5;
        float pp = 0.f;
        #pragma unroll
        for (int j = 0; j < 32; j++)
            pp += wfin[g * 32 + j] * Wv[(g * 32 + j) * Hz + hr * HDz + c];
        wp2[t] = pp;
    }
    __syncthreads();
    if (t < HDz) {
        float ww = wp2[t] + wp2[t + 32] + wp2[t + 64] + wp2[t + 96];
        g_ctxbase[(b * Sz + q) * Hz + hr * HDz + t] = ww * invL + bv[hr * HDz + t];
    }
}

// ---------------------------------------------------------------------------
// K3: ctx = ctxbase + probs(scaled) @ Veff. grid (8,8,4), 256 threads.
// ---------------------------------------------------------------------------
__global__ void __launch_bounds__(256) ctxv_kernel() {
    int qt = blockIdx.x, b = blockIdx.y, h = blockIdx.z;
    int t = threadIdx.x;
    extern __shared__ float sm3[];
    float* Vs  = sm3;                  // 256*33
    float* Ps  = sm3 + 256 * 33;       // 32*256
    float* psc = sm3 + 256 * 33 + 32 * 256;  // 64

    if (t < 64) {
        int qq = t >> 1, hh = t & 1;
        psc[t] = g_pscale[((b * 4 + h) * Sz + qt * 32 + qq) * 2 + hh];
    }
    #pragma unroll
    for (int jj = 0; jj < 8; jj++) {
        int idx = jj * 256 + t;
        int row = idx >> 3, c4 = idx & 7;
        float4 v = *(const float4*)&g_Veff[(b * Sz + row) * Hz + h * HDz + c4 * 4];
        Vs[row * 33 + c4 * 4 + 0] = v.x;
        Vs[row * 33 + c4 * 4 + 1] = v.y;
        Vs[row * 33 + c4 * 4 + 2] = v.z;
        Vs[row * 33 + c4 * 4 + 3] = v.w;
    }
    __syncthreads();
    #pragma unroll
    for (int jj = 0; jj < 8; jj++) {
        int idx = jj * 256 + t;
        int qq = idx >> 6, k4 = idx & 63;
        float4 v = *(const float4*)&g_probs[((b * 4 + h) * Sz + qt * 32 + qq) * Sz + k4 * 4];
        float sc = psc[qq * 2 + (k4 >= 32 ? 1 : 0)];
        v.x *= sc; v.y *= sc; v.z *= sc; v.w *= sc;
        *(float4*)&Ps[qq * 256 + k4 * 4] = v;
    }
    __syncthreads();

    int c = t & 31, q0 = t >> 5;
    const float4* Ps4 = (const float4*)Ps;
    float acc0 = 0.f, acc1 = 0.f, acc2 = 0.f, acc3 = 0.f;
    #pragma unroll 4
    for (int k4 = 0; k4 < 64; k4++) {
        float v0 = Vs[(k4 * 4 + 0) * 33 + c];
        float v1 = Vs[(k4 * 4 + 1) * 33 + c];
        float v2 = Vs[(k4 * 4 + 2) * 33 + c];
        float v3 = Vs[(k4 * 4 + 3) * 33 + c];
        float4 P0 = Ps4[(q0     ) * 64 + k4];
        float4 P1 = Ps4[(q0 +  8) * 64 + k4];
        float4 P2 = Ps4[(q0 + 16) * 64 + k4];
        float4 P3 = Ps4[(q0 + 24) * 64 + k4];
        acc0 += P0.x * v0 + P0.y * v1 + P0.z * v2 + P0.w * v3;
        acc1 += P1.x * v0 + P1.y * v1 + P1.z * v2 + P1.w * v3;
        acc2 += P2.x * v0 + P2.y * v1 + P2.z * v2 + P2.w * v3;
        acc3 += P3.x * v0 + P3.y * v1 + P3.z * v2 + P3.w * v3;
    }
    #pragma unroll
    for (int r = 0; r < 4; r++) {
        int q = qt * 32 + q0 + r * 8;
        float a = (r == 0) ? acc0 : (r == 1) ? acc1 : (r == 2) ? acc2 : acc3;
        g_ctx[(b * Sz + q) * Hz + h * HDz + c] =
            g_ctxbase[(b * Sz + q) * Hz + h * HDz + c] + a;
    }
}

// ---------------------------------------------------------------------------
// K4: out = ctx @ Wo + bo. 4 rows per CTA.
// ---------------------------------------------------------------------------
__global__ void out_kernel(const float* __restrict__ Wo,
                           const float* __restrict__ bo,
                           float* __restrict__ out) {
    int r0 = blockIdx.x * 4;
    int j = threadIdx.x;
    __shared__ float xs[4][Hz];
    #pragma unroll
    for (int r = 0; r < 4; r++) xs[r][j] = g_ctx[(r0 + r) * Hz + j];
    __syncthreads();
    float a0 = bo[j], a1 = a0, a2 = a0, a3 = a0;
    #pragma unroll 4
    for (int i = 0; i < Hz; i++) {
        float w = Wo[i * Hz + j];
        a0 += xs[0][i] * w; a1 += xs[1][i] * w;
        a2 += xs[2][i] * w; a3 += xs[3][i] * w;
    }
    out[r0 * Hz + j] = a0;
    out[(r0 + 1) * Hz + j] = a1;
    out[(r0 + 2) * Hz + j] = a2;
    out[(r0 + 3) * Hz + j] = a3;
}

// ---------------------------------------------------------------------------
extern "C" void kernel_launch(void* const* d_in, const int* in_sizes, int n_in,
                              void* d_out, int out_size) {
    const float* X    = (const float*)d_in[0];
    const float* mask = (const float*)d_in[1];
    const float* abs0 = (const float*)d_in[2];
    const float* abs1 = (const float*)d_in[3];
    const float* rel0 = (const float*)d_in[4];
    const float* rel1 = (const float*)d_in[5];
    const float* Wq   = (const float*)d_in[6];
    const float* bq   = (const float*)d_in[7];
    const float* Wk   = (const float*)d_in[8];
    const float* bk   = (const float*)d_in[9];
    const float* Wv   = (const float*)d_in[10];
    const float* bv   = (const float*)d_in[11];
    const float* Wo   = (const float*)d_in[12];
    const float* bo   = (const float*)d_in[13];
    float* out = (float*)d_out;

    size_t relsm = (size_t)(128 * TST + 128 + 128 + 128 + 4 + 4) * sizeof(float);
    size_t ctxsm = (size_t)(256 * 33 + 32 * 256 + 64) * sizeof(float);
    cudaFuncSetAttribute(rel_kernel,  cudaFuncAttributeMaxDynamicSharedMemorySize, (int)relsm);
    cudaFuncSetAttribute(ctxv_kernel, cudaFuncAttributeMaxDynamicSharedMemorySize, (int)ctxsm);

    proj_kernel<<<BSz / 2, Hz>>>(X, abs0, abs1, Wq, bq, Wk, bk, Wv, bv);
    dim3 gs(8, Bz, 4);
    sbase_kernel<<<gs, 256>>>(mask);
    dim3 gu(8, Bz, 2);
    u_kernel<<<gu, 128>>>(Wk);                 // launch slot 3 -> rel is slot 4 (ncu capture)
    dim3 gr(Sz, Bz, 4);                        // z = i*2 + half
    rel_kernel<<<gr, 128, relsm>>>(rel0, rel1);
    dim3 gc(Sz, Bz, 2);
    combine_kernel<<<gc, 128>>>(Wv, bv);
    ctxv_kernel<<<gs, 256, ctxsm>>>();
    out_kernel<<<BSz / 4, Hz>>>(Wo, bo, out);
}

// round 8
// speedup vs baseline: 2.1004x; 1.0428x over previous
#include <cuda_runtime.h>
#include <cstdint>

#define Bz  8
#define Sz  256
#define Hz  128
#define HDz 32
#define BSz 2048
#define SCALE 0.17677669529663687f   // 1/sqrt(32)
#define TST 132                       // rel tile row stride (floats)

// __device__ scratch (allocation-free rule)
__device__ float g_Q[BSz * Hz];
__device__ float g_Keff[BSz * Hz];
__device__ float g_Veff[BSz * Hz];
__device__ float g_u[Bz * 2 * Sz * Hz];        // u[b,i,q][128]
__device__ float g_sbase[Bz * 4 * Sz * Sz];    // rel heads only: [b][h][q][k]
__device__ float g_probs[Bz * 4 * Sz * Sz];    // abs: normalized; rel: pexp (scaled in ctxv)
__device__ float g_pscale[Bz * 4 * Sz * 2];    // rel heads: per (b,h,q,half) prob scale
__device__ float g_mred[Bz * 2 * Sz * 2 * 2];  // (m,l) per (b,i,q,half)
__device__ float g_wpart[Bz * 2 * Sz * 2 * Hz];// wacc per (b,i,q,half)[128]
__device__ float g_ctxbase[BSz * Hz];          // rel heads only
__device__ float g_ctx[BSz * Hz];

#define CP_ASYNC16(dst, src) \
    asm volatile("cp.async.cg.shared.global [%0], [%1], 16;\n" :: "r"(dst), "l"(src))
#define CP_COMMIT() asm volatile("cp.async.commit_group;\n" ::: "memory")
#define CP_WAIT0()  asm volatile("cp.async.wait_group 0;\n" ::: "memory")

// ---------------------------------------------------------------------------
// K0: projections. 2 rows per CTA, 128 threads.
// ---------------------------------------------------------------------------
__global__ void proj_kernel(const float* __restrict__ X,
                            const float* __restrict__ abs0,
                            const float* __restrict__ abs1,
                            const float* __restrict__ Wq, const float* __restrict__ bq,
                            const float* __restrict__ Wk, const float* __restrict__ bk,
                            const float* __restrict__ Wv, const float* __restrict__ bv) {
    int r0 = blockIdx.x * 2;
    int j  = threadIdx.x;
    __shared__ float xs[2][Hz], a0s[2][Hz], a1s[2][Hz];
    #pragma unroll
    for (int r = 0; r < 2; r++) {
        xs[r][j]  = X[(r0 + r) * Hz + j];
        a0s[r][j] = abs0[(r0 + r) * Hz + j];
        a1s[r][j] = abs1[(r0 + r) * Hz + j];
    }
    __syncthreads();

    float q0 = bq[j], k0 = bk[j], v0 = bv[j];
    float q1 = q0, k1 = k0, v1 = v0;
    #pragma unroll 4
    for (int i = 0; i < Hz; i++) {
        float wq = Wq[i * Hz + j], wk = Wk[i * Hz + j], wv = Wv[i * Hz + j];
        float x0 = xs[0][i], x1 = xs[1][i];
        q0 += x0 * wq; k0 += x0 * wk; v0 += x0 * wv;
        q1 += x1 * wq; k1 += x1 * wk; v1 += x1 * wv;
    }
    if (j < 64) {   // abs-head folds
        float ka0 = bk[j], va0 = bv[j], ka1 = ka0, va1 = va0;
        #pragma unroll 4
        for (int i = 0; i < Hz; i++) {
            float wk = Wk[i * Hz + j], wv = Wv[i * Hz + j];
            float b0 = (j < 32) ? a0s[0][i] : a1s[0][i];
            float b1 = (j < 32) ? a0s[1][i] : a1s[1][i];
            ka0 += b0 * wk; va0 += b0 * wv;
            ka1 += b1 * wk; va1 += b1 * wv;
        }
        k0 += ka0; v0 += va0; k1 += ka1; v1 += va1;
    }
    g_Q[r0 * Hz + j] = q0;        g_Q[(r0 + 1) * Hz + j] = q1;
    g_Keff[r0 * Hz + j] = k0;     g_Keff[(r0 + 1) * Hz + j] = k1;
    g_Veff[r0 * Hz + j] = v0;     g_Veff[(r0 + 1) * Hz + j] = v1;
}

// ---------------------------------------------------------------------------
// K1: scores. For rel heads (h>=2): write sbase = QK*SCALE + mask.
// For abs heads (h<2): finish softmax in-CTA, write NORMALIZED probs.
// grid (qt=8, b=8, h=4), 256 threads.
// ---------------------------------------------------------------------------
__global__ void __launch_bounds__(256) sbase_kernel(const float* __restrict__ mask) {
    int qt = blockIdx.x, b = blockIdx.y, h = blockIdx.z;
    int t = threadIdx.x;
    extern __shared__ float smb[];
    float* Qs = smb;                  // 32*32
    float* ks = Qs + 32 * 32;         // 256*33
    float* ss = ks + 256 * 33;        // 32*257 (abs only)

    #pragma unroll
    for (int r = 0; r < 4; r++) {
        int idx = r * 256 + t;
        int qq = idx >> 5, c = idx & 31;
        Qs[idx] = g_Q[(b * Sz + qt * 32 + qq) * Hz + h * HDz + c];
    }
    #pragma unroll
    for (int jj = 0; jj < 8; jj++) {
        int idx = jj * 256 + t;
        int row = idx >> 3, c4 = idx & 7;
        float4 v = *(const float4*)&g_Keff[(b * Sz + row) * Hz + h * HDz + c4 * 4];
        ks[row * 33 + c4 * 4 + 0] = v.x;
        ks[row * 33 + c4 * 4 + 1] = v.y;
        ks[row * 33 + c4 * 4 + 2] = v.z;
        ks[row * 33 + c4 * 4 + 3] = v.w;
    }
    __syncthreads();

    float kr[32];
    #pragma unroll
    for (int c = 0; c < 32; c++) kr[c] = ks[t * 33 + c];

    int qbase = qt * 32;
    if (h >= 2) {
        #pragma unroll 2
        for (int qq = 0; qq < 32; qq++) {
            float acc = 0.f;
            #pragma unroll
            for (int c = 0; c < 32; c++) acc += Qs[qq * 32 + c] * kr[c];
            int q = qbase + qq;
            g_sbase[((b * 4 + h) * Sz + q) * Sz + t] =
                acc * SCALE + mask[(b * Sz + q) * Sz + t];
        }
    } else {
        #pragma unroll 2
        for (int qq = 0; qq < 32; qq++) {
            float acc = 0.f;
            #pragma unroll
            for (int c = 0; c < 32; c++) acc += Qs[qq * 32 + c] * kr[c];
            int q = qbase + qq;
            ss[qq * 257 + t] = acc * SCALE + mask[(b * Sz + q) * Sz + t];
        }
        __syncthreads();
        // softmax: 8 warps x 4 q-rows; each lane holds 8 keys of the row
        int w = t >> 5, lane = t & 31;
        #pragma unroll
        for (int r = 0; r < 4; r++) {
            int row = w * 4 + r;
            float v[8];
            #pragma unroll
            for (int j = 0; j < 8; j++) v[j] = ss[row * 257 + lane + j * 32];
            float m = v[0];
            #pragma unroll
            for (int j = 1; j < 8; j++) m = fmaxf(m, v[j]);
            #pragma unroll
            for (int o = 16; o; o >>= 1) m = fmaxf(m, __shfl_xor_sync(~0u, m, o));
            float p[8], l = 0.f;
            #pragma unroll
            for (int j = 0; j < 8; j++) { p[j] = __expf(v[j] - m); l += p[j]; }
            #pragma unroll
            for (int o = 16; o; o >>= 1) l += __shfl_xor_sync(~0u, l, o);
            float inv = 1.f / l;
            int q = qbase + row;
            #pragma unroll
            for (int j = 0; j < 8; j++)
                g_probs[((b * 4 + h) * Sz + q) * Sz + lane + j * 32] = p[j] * inv;
        }
    }
}

// ---------------------------------------------------------------------------
// K1b: u[b,i,q,j] = sum_c Wk[j, hr*32+c] * Q[b,q,hr*32+c]
// ---------------------------------------------------------------------------
__global__ void __launch_bounds__(128) u_kernel(const float* __restrict__ Wk) {
    int qt = blockIdx.x, b = blockIdx.y, i = blockIdx.z;
    int hr = 2 + i;
    int j = threadIdx.x;
    __shared__ float Qs[32][32];

    #pragma unroll
    for (int r = 0; r < 8; r++) {
        int idx = r * 128 + j;
        int qq = idx >> 5, c = idx & 31;
        Qs[qq][c] = g_Q[(b * Sz + qt * 32 + qq) * Hz + hr * HDz + c];
    }
    __syncthreads();

    float wr[32];
    #pragma unroll
    for (int c = 0; c < 32; c++) wr[c] = Wk[j * Hz + hr * HDz + c];

    #pragma unroll 4
    for (int qq = 0; qq < 32; qq++) {
        float acc = 0.f;
        #pragma unroll
        for (int c = 0; c < 32; c++) acc += wr[c] * Qs[qq][c];
        g_u[((b * 2 + i) * Sz + qt * 32 + qq) * Hz + j] = acc;
    }
}

// ---------------------------------------------------------------------------
// K2: rel split-K (halves). CTA per (q, b, i*2+half); 128 threads (4 warps).
// (unchanged — measured 86us @ 81.6% DRAM, at roofline)
// ---------------------------------------------------------------------------
__global__ void __launch_bounds__(128, 3) rel_kernel(
        const float* __restrict__ rel0, const float* __restrict__ rel1) {
    int q = blockIdx.x, b = blockIdx.y;
    int i = blockIdx.z >> 1, half = blockIdx.z & 1;
    int hr = 2 + i;
    int kbase = half * 128;
    int t = threadIdx.x, lane = t & 31, w = t >> 5;

    extern __shared__ float sm[];
    float* tile = sm;                 // [128][TST]
    float* uvec = sm + 128 * TST;     // 128
    float* kb   = uvec + 128;         // 128
    float* pc   = kb + 128;           // 128
    float* wm   = pc + 128;           // 4
    float* wl   = wm + 4;             // 4

    const float4* rp4 = (const float4*)(((i == 0) ? rel0 : rel1)
                        + (size_t)(b * Sz + q) * Sz * Hz) + (size_t)kbase * 32;
    uint32_t tileu = (uint32_t)__cvta_generic_to_shared(tile);
    #pragma unroll
    for (int r = 0; r < 32; r++) {
        int row = w * 32 + r;
        uint32_t d = tileu + (uint32_t)(row * TST + lane * 4) * 4;
        CP_ASYNC16(d, rp4 + row * 32 + lane);
    }
    CP_COMMIT();

    uvec[t] = g_u[((b * 2 + i) * Sz + q) * Hz + t];
    kb[t]   = g_sbase[((b * 4 + hr) * Sz + q) * Sz + kbase + t];
    __syncthreads();

    CP_WAIT0();
    __syncwarp();
    float s;
    {
        const float4* row = (const float4*)&tile[t * TST];
        const float4* u4  = (const float4*)uvec;
        float acc = 0.f;
        #pragma unroll
        for (int j = 0; j < 32; j++) {
            float4 r = row[j], u = u4[j];
            acc += r.x * u.x + r.y * u.y + r.z * u.z + r.w * u.w;
        }
        s = acc * SCALE + kb[t];
    }
    float mw = s;
    #pragma unroll
    for (int o = 16; o; o >>= 1) mw = fmaxf(mw, __shfl_xor_sync(~0u, mw, o));
    if (lane == 0) wm[w] = mw;
    __syncthreads();

    float M = fmaxf(fmaxf(wm[0], wm[1]), fmaxf(wm[2], wm[3]));
    float p = __expf(s - M);
    pc[t] = p;
    float lw = p;
    #pragma unroll
    for (int o = 16; o; o >>= 1) lw += __shfl_xor_sync(~0u, lw, o);
    if (lane == 0) wl[w] = lw;
    __syncthreads();
    float L = wl[0] + wl[1] + wl[2] + wl[3];

    g_probs[((b * 4 + hr) * Sz + q) * Sz + kbase + t] = p;
    if (t == 0) {
        int mi = ((b * 2 + i) * Sz + q) * 2 + half;
        g_mred[mi * 2 + 0] = M;
        g_mred[mi * 2 + 1] = L;
    }

    {
        float wacc = 0.f;
        #pragma unroll 8
        for (int k = 0; k < 128; k++)
            wacc += pc[k] * tile[k * TST + t];
        g_wpart[(((b * 2 + i) * Sz + q) * 2 + half) * Hz + t] = wacc;
    }
}

// ---------------------------------------------------------------------------
// K2b: combine (rel only now). CTA per (q, b, i); 128 threads.
// ---------------------------------------------------------------------------
__global__ void __launch_bounds__(128) combine_kernel(
        const float* __restrict__ Wv, const float* __restrict__ bv) {
    int q = blockIdx.x, b = blockIdx.y, i = blockIdx.z;
    int hr = 2 + i;
    int t = threadIdx.x;

    __shared__ float wfin[Hz];
    __shared__ float wp2[Hz];

    int mi = ((b * 2 + i) * Sz + q) * 2;
    float m0 = g_mred[(mi + 0) * 2 + 0], l0 = g_mred[(mi + 0) * 2 + 1];
    float m1 = g_mred[(mi + 1) * 2 + 0], l1 = g_mred[(mi + 1) * 2 + 1];
    float M = fmaxf(m0, m1);
    float c0 = __expf(m0 - M), c1 = __expf(m1 - M);
    float invL = 1.f / (l0 * c0 + l1 * c1);

    wfin[t] = g_wpart[(mi + 0) * Hz + t] * c0 + g_wpart[(mi + 1) * Hz + t] * c1;

    if (t == 0) {
        g_pscale[((b * 4 + hr) * Sz + q) * 2 + 0] = c0 * invL;
        g_pscale[((b * 4 + hr) * Sz + q) * 2 + 1] = c1 * invL;
    }
    __syncthreads();

    // project wfin through Wv_hr (4 groups of 32 channels)
    {
        int c = t & 31, g = t >> 5;
        float pp = 0.f;
        #pragma unroll
        for (int j = 0; j < 32; j++)
            pp += wfin[g * 32 + j] * Wv[(g * 32 + j) * Hz + hr * HDz + c];
        wp2[t] = pp;
    }
    __syncthreads();
    if (t < HDz) {
        float ww = wp2[t] + wp2[t + 32] + wp2[t + 64] + wp2[t + 96];
        g_ctxbase[(b * Sz + q) * Hz + hr * HDz + t] = ww * invL + bv[hr * HDz + t];
    }
}

// ---------------------------------------------------------------------------
// K3: ctx = [ctxbase +] probs(scaled) @ Veff. grid (16,8,4), 256 thr, 16 q/CTA.
// ---------------------------------------------------------------------------
__global__ void __launch_bounds__(256) ctxv_kernel() {
    int qt = blockIdx.x, b = blockIdx.y, h = blockIdx.z;
    int qbase = qt * 16;
    int t = threadIdx.x;
    extern __shared__ float sm3[];
    float* Vs  = sm3;                        // 256*33
    float* Ps  = sm3 + 256 * 33;             // 16*256
    float* psc = sm3 + 256 * 33 + 16 * 256;  // 32

    if (h >= 2 && t < 32)
        psc[t] = g_pscale[((b * 4 + h) * Sz + qbase + (t >> 1)) * 2 + (t & 1)];
    #pragma unroll
    for (int jj = 0; jj < 8; jj++) {
        int idx = jj * 256 + t;
        int row = idx >> 3, c4 = idx & 7;
        float4 v = *(const float4*)&g_Veff[(b * Sz + row) * Hz + h * HDz + c4 * 4];
        Vs[row * 33 + c4 * 4 + 0] = v.x;
        Vs[row * 33 + c4 * 4 + 1] = v.y;
        Vs[row * 33 + c4 * 4 + 2] = v.z;
        Vs[row * 33 + c4 * 4 + 3] = v.w;
    }
    __syncthreads();
    #pragma unroll
    for (int jj = 0; jj < 4; jj++) {
        int idx = jj * 256 + t;                  // 1024 float4
        int qq = idx >> 6, k4 = idx & 63;
        float4 v = *(const float4*)&g_probs[((b * 4 + h) * Sz + qbase + qq) * Sz + k4 * 4];
        if (h >= 2) {
            float sc = psc[qq * 2 + (k4 >= 32 ? 1 : 0)];
            v.x *= sc; v.y *= sc; v.z *= sc; v.w *= sc;
        }
        *(float4*)&Ps[qq * 256 + k4 * 4] = v;
    }
    __syncthreads();

    int c = t & 31, g = t >> 5;                  // 8 groups x 2 q each
    const float4* Ps4 = (const float4*)Ps;
    float acc0 = 0.f, acc1 = 0.f;
    #pragma unroll 4
    for (int k4 = 0; k4 < 64; k4++) {
        float v0 = Vs[(k4 * 4 + 0) * 33 + c];
        float v1 = Vs[(k4 * 4 + 1) * 33 + c];
        float v2 = Vs[(k4 * 4 + 2) * 33 + c];
        float v3 = Vs[(k4 * 4 + 3) * 33 + c];
        float4 P0 = Ps4[(g * 2 + 0) * 64 + k4];
        float4 P1 = Ps4[(g * 2 + 1) * 64 + k4];
        acc0 += P0.x * v0 + P0.y * v1 + P0.z * v2 + P0.w * v3;
        acc1 += P1.x * v0 + P1.y * v1 + P1.z * v2 + P1.w * v3;
    }
    #pragma unroll
    for (int r = 0; r < 2; r++) {
        int q = qbase + g * 2 + r;
        float a = (r == 0) ? acc0 : acc1;
        float base = (h >= 2) ? g_ctxbase[(b * Sz + q) * Hz + h * HDz + c] : 0.f;
        g_ctx[(b * Sz + q) * Hz + h * HDz + c] = base + a;
    }
}

// ---------------------------------------------------------------------------
// K4: out = ctx @ Wo + bo. Wo staged in smem; 16 rows/CTA, 256 threads.
// ---------------------------------------------------------------------------
__global__ void __launch_bounds__(256) out_kernel(const float* __restrict__ Wo,
                                                  const float* __restrict__ bo,
                                                  float* __restrict__ out) {
    int r0 = blockIdx.x * 16;
    int t = threadIdx.x;
    extern __shared__ float sm4[];
    float* ws = sm4;                 // 128*128
    float* xs = sm4 + Hz * Hz;       // 16*128

    #pragma unroll
    for (int jj = 0; jj < 16; jj++) {
        int idx = jj * 256 + t;      // 4096 float4
        *(float4*)&ws[idx * 4] = *(const float4*)&Wo[idx * 4];
    }
    #pragma unroll
    for (int jj = 0; jj < 2; jj++) {
        int idx = jj * 256 + t;      // 512 float4
        *(float4*)&xs[idx * 4] = *(const float4*)&g_ctx[r0 * Hz + idx * 4];
    }
    __syncthreads();

    int j = t & 127, rbase = (t >> 7) * 8;   // 2 row-groups of 8
    float a[8];
    float bj = bo[j];
    #pragma unroll
    for (int r = 0; r < 8; r++) a[r] = bj;
    #pragma unroll 4
    for (int i = 0; i < Hz; i++) {
        float w = ws[i * Hz + j];
        #pragma unroll
        for (int r = 0; r < 8; r++)
            a[r] += xs[(rbase + r) * Hz + i] * w;
    }
    #pragma unroll
    for (int r = 0; r < 8; r++)
        out[(r0 + rbase + r) * Hz + j] = a[r];
}

// ---------------------------------------------------------------------------
extern "C" void kernel_launch(void* const* d_in, const int* in_sizes, int n_in,
                              void* d_out, int out_size) {
    const float* X    = (const float*)d_in[0];
    const float* mask = (const float*)d_in[1];
    const float* abs0 = (const float*)d_in[2];
    const float* abs1 = (const float*)d_in[3];
    const float* rel0 = (const float*)d_in[4];
    const float* rel1 = (const float*)d_in[5];
    const float* Wq   = (const float*)d_in[6];
    const float* bq   = (const float*)d_in[7];
    const float* Wk   = (const float*)d_in[8];
    const float* bk   = (const float*)d_in[9];
    const float* Wv   = (const float*)d_in[10];
    const float* bv   = (const float*)d_in[11];
    const float* Wo   = (const float*)d_in[12];
    const float* bo   = (const float*)d_in[13];
    float* out = (float*)d_out;

    size_t sbsm  = (size_t)(32 * 32 + 256 * 33 + 32 * 257) * sizeof(float);
    size_t relsm = (size_t)(128 * TST + 128 + 128 + 128 + 4 + 4) * sizeof(float);
    size_t ctxsm = (size_t)(256 * 33 + 16 * 256 + 32) * sizeof(float);
    size_t outsm = (size_t)(Hz * Hz + 16 * Hz) * sizeof(float);
    cudaFuncSetAttribute(sbase_kernel, cudaFuncAttributeMaxDynamicSharedMemorySize, (int)sbsm);
    cudaFuncSetAttribute(rel_kernel,   cudaFuncAttributeMaxDynamicSharedMemorySize, (int)relsm);
    cudaFuncSetAttribute(ctxv_kernel,  cudaFuncAttributeMaxDynamicSharedMemorySize, (int)ctxsm);
    cudaFuncSetAttribute(out_kernel,   cudaFuncAttributeMaxDynamicSharedMemorySize, (int)outsm);

    proj_kernel<<<BSz / 2, Hz>>>(X, abs0, abs1, Wq, bq, Wk, bk, Wv, bv);
    dim3 gs(8, Bz, 4);
    sbase_kernel<<<gs, 256, sbsm>>>(mask);
    dim3 gu(8, Bz, 2);
    u_kernel<<<gu, 128>>>(Wk);
    dim3 gr(Sz, Bz, 4);                        // z = i*2 + half
    rel_kernel<<<gr, 128, relsm>>>(rel0, rel1);
    dim3 gc(Sz, Bz, 2);
    combine_kernel<<<gc, 128>>>(Wv, bv);
    dim3 gv(16, Bz, 4);
    ctxv_kernel<<<gv, 256, ctxsm>>>();
    out_kernel<<<BSz / 16, 256, outsm>>>(Wo, bo, out);
}

// round 9
// speedup vs baseline: 2.6845x; 1.2781x over previous
#include <cuda_runtime.h>
#include <cstdint>

#define Bz  8
#define Sz  256
#define Hz  128
#define HDz 32
#define BSz 2048
#define SCALE 0.17677669529663687f   // 1/sqrt(32)
#define TST 132                       // rel tile row stride (floats)
#define XPAD 129                      // proj input row stride (conflict-free lane-per-row)

// __device__ scratch (allocation-free rule)
__device__ float g_Q[BSz * Hz];
__device__ float g_Keff[BSz * Hz];
__device__ float g_Veff[BSz * Hz];
__device__ float g_u[Bz * 2 * Sz * Hz];        // u[b,i,q][128]
__device__ float g_sbase[Bz * 4 * Sz * Sz];    // rel heads only: [b][h][q][k]
__device__ float g_probs[Bz * 4 * Sz * Sz];    // abs: normalized; rel: pexp (scaled in ctxv)
__device__ float g_pscale[Bz * 4 * Sz * 2];    // rel heads: per (b,h,q,half) prob scale
__device__ float g_mred[Bz * 2 * Sz * 2 * 2];  // (m,l) per (b,i,q,half)
__device__ float g_wpart[Bz * 2 * Sz * 2 * Hz];// wacc per (b,i,q,half)[128]
__device__ float g_ctxbase[BSz * Hz];          // rel heads only
__device__ float g_ctx[BSz * Hz];

#define CP_ASYNC16(dst, src) \
    asm volatile("cp.async.cg.shared.global [%0], [%1], 16;\n" :: "r"(dst), "l"(src))
#define CP_COMMIT() asm volatile("cp.async.commit_group;\n" ::: "memory")
#define CP_WAIT0()  asm volatile("cp.async.wait_group 0;\n" ::: "memory")

// ---------------------------------------------------------------------------
// K0: projections, register-tiled. 16 rows/CTA (128 CTAs), 256 threads.
// Thread = (row r = t&15, jgroup jg = t>>4 -> 8 output cols). Weights staged
// in smem in 32-i tiles; warp-uniform abs-fold predicates (warps 0-3 fold).
// ---------------------------------------------------------------------------
__global__ void __launch_bounds__(256, 2) proj_kernel(
        const float* __restrict__ X,
        const float* __restrict__ abs0,
        const float* __restrict__ abs1,
        const float* __restrict__ Wq, const float* __restrict__ bq,
        const float* __restrict__ Wk, const float* __restrict__ bk,
        const float* __restrict__ Wv, const float* __restrict__ bv) {
    int r0 = blockIdx.x * 16;
    int t = threadIdx.x;
    extern __shared__ float smp[];
    float* xs  = smp;                    // 16 * XPAD
    float* a0s = xs  + 16 * XPAD;        // 16 * XPAD
    float* a1s = a0s + 16 * XPAD;        // 16 * XPAD
    float* wts = a1s + 16 * XPAD;        // 3 * 32 * 128

    // load inputs (scalar, coalesced: consecutive t -> consecutive col)
    #pragma unroll
    for (int jj = 0; jj < 8; jj++) {
        int idx = jj * 256 + t;          // 2048
        int row = idx >> 7, col = idx & 127;
        xs [row * XPAD + col] = X   [(r0 + row) * Hz + col];
        a0s[row * XPAD + col] = abs0[(r0 + row) * Hz + col];
        a1s[row * XPAD + col] = abs1[(r0 + row) * Hz + col];
    }

    int r = t & 15, jg = t >> 4;         // jg uniform per half-warp; fold uniform per warp
    int j0 = jg * 8;
    bool fold = (jg < 8);                // j0 < 64
    const float* as = (jg < 4) ? a0s : a1s;

    float qa[8], ka[8], va[8];
    #pragma unroll
    for (int jj = 0; jj < 8; jj++) {
        qa[jj] = bq[j0 + jj];
        float bkv = bk[j0 + jj], bvv = bv[j0 + jj];
        ka[jj] = fold ? 2.f * bkv : bkv; // fold adds the abs-head bias (same slice)
        va[jj] = fold ? 2.f * bvv : bvv;
    }

    for (int i0 = 0; i0 < Hz; i0 += 32) {
        __syncthreads();                 // inputs ready / previous tile consumed
        #pragma unroll
        for (int jj = 0; jj < 4; jj++) { // 1024 float4 per matrix
            int idx = jj * 256 + t;
            ((float4*)wts)[idx]               = ((const float4*)(Wq + i0 * Hz))[idx];
            ((float4*)(wts + 32 * Hz))[idx]   = ((const float4*)(Wk + i0 * Hz))[idx];
            ((float4*)(wts + 64 * Hz))[idx]   = ((const float4*)(Wv + i0 * Hz))[idx];
        }
        __syncthreads();
        #pragma unroll 8
        for (int ii = 0; ii < 32; ii++) {
            int i = i0 + ii;
            float x = xs[r * XPAD + i];
            float wq[8], wk8[8], wv8[8];
            *(float4*)&wq [0] = *(const float4*)&wts[ii * Hz + j0];
            *(float4*)&wq [4] = *(const float4*)&wts[ii * Hz + j0 + 4];
            *(float4*)&wk8[0] = *(const float4*)&wts[32 * Hz + ii * Hz + j0];
            *(float4*)&wk8[4] = *(const float4*)&wts[32 * Hz + ii * Hz + j0 + 4];
            *(float4*)&wv8[0] = *(const float4*)&wts[64 * Hz + ii * Hz + j0];
            *(float4*)&wv8[4] = *(const float4*)&wts[64 * Hz + ii * Hz + j0 + 4];
            #pragma unroll
            for (int jj = 0; jj < 8; jj++) {
                qa[jj] += x * wq[jj];
                ka[jj] += x * wk8[jj];
                va[jj] += x * wv8[jj];
            }
            if (fold) {
                float a = as[r * XPAD + i];
                #pragma unroll
                for (int jj = 0; jj < 8; jj++) {
                    ka[jj] += a * wk8[jj];
                    va[jj] += a * wv8[jj];
                }
            }
        }
    }

    int ro = r0 + r;
    *(float4*)&g_Q[ro * Hz + j0]        = *(float4*)&qa[0];
    *(float4*)&g_Q[ro * Hz + j0 + 4]    = *(float4*)&qa[4];
    *(float4*)&g_Keff[ro * Hz + j0]     = *(float4*)&ka[0];
    *(float4*)&g_Keff[ro * Hz + j0 + 4] = *(float4*)&ka[4];
    *(float4*)&g_Veff[ro * Hz + j0]     = *(float4*)&va[0];
    *(float4*)&g_Veff[ro * Hz + j0 + 4] = *(float4*)&va[4];
}

// ---------------------------------------------------------------------------
// K1: scores. Rel heads (h>=2): write sbase AND the u-vector for their q's.
// Abs heads (h<2): finish softmax in-CTA, write NORMALIZED probs.
// grid (qt=8, b=8, h=4), 256 threads.
// ---------------------------------------------------------------------------
__global__ void __launch_bounds__(256) sbase_kernel(const float* __restrict__ mask,
                                                    const float* __restrict__ Wk) {
    int qt = blockIdx.x, b = blockIdx.y, h = blockIdx.z;
    int t = threadIdx.x;
    extern __shared__ float smb[];
    float* Qs = smb;                  // 32*32
    float* ks = Qs + 32 * 32;         // 256*33
    float* ss = ks + 256 * 33;        // 32*257 (abs only)

    #pragma unroll
    for (int r = 0; r < 4; r++) {
        int idx = r * 256 + t;
        int qq = idx >> 5, c = idx & 31;
        Qs[idx] = g_Q[(b * Sz + qt * 32 + qq) * Hz + h * HDz + c];
    }
    #pragma unroll
    for (int jj = 0; jj < 8; jj++) {
        int idx = jj * 256 + t;
        int row = idx >> 3, c4 = idx & 7;
        float4 v = *(const float4*)&g_Keff[(b * Sz + row) * Hz + h * HDz + c4 * 4];
        ks[row * 33 + c4 * 4 + 0] = v.x;
        ks[row * 33 + c4 * 4 + 1] = v.y;
        ks[row * 33 + c4 * 4 + 2] = v.z;
        ks[row * 33 + c4 * 4 + 3] = v.w;
    }
    __syncthreads();

    float kr[32];
    #pragma unroll
    for (int c = 0; c < 32; c++) kr[c] = ks[t * 33 + c];

    int qbase = qt * 32;
    if (h >= 2) {
        #pragma unroll 2
        for (int qq = 0; qq < 32; qq++) {
            float acc = 0.f;
            #pragma unroll
            for (int c = 0; c < 32; c++) acc += Qs[qq * 32 + c] * kr[c];
            int q = qbase + qq;
            g_sbase[((b * 4 + h) * Sz + q) * Sz + t] =
                acc * SCALE + mask[(b * Sz + q) * Sz + t];
        }
        // u[b,i,q,j] = sum_c Wk[j, h*32+c] * Q[b,q,h*32+c]  (Qs already loaded)
        int j = t & 127, g2 = t >> 7;    // 2 groups x 16 q
        int i = h - 2;
        float wr[32];
        #pragma unroll
        for (int c4 = 0; c4 < 8; c4++)
            *(float4*)&wr[c4 * 4] = *(const float4*)&Wk[j * Hz + h * HDz + c4 * 4];
        #pragma unroll 4
        for (int qq = g2 * 16; qq < g2 * 16 + 16; qq++) {
            float acc = 0.f;
            #pragma unroll
            for (int c = 0; c < 32; c++) acc += wr[c] * Qs[qq * 32 + c];
            g_u[((b * 2 + i) * Sz + qbase + qq) * Hz + j] = acc;
        }
    } else {
        #pragma unroll 2
        for (int qq = 0; qq < 32; qq++) {
            float acc = 0.f;
            #pragma unroll
            for (int c = 0; c < 32; c++) acc += Qs[qq * 32 + c] * kr[c];
            int q = qbase + qq;
            ss[qq * 257 + t] = acc * SCALE + mask[(b * Sz + q) * Sz + t];
        }
        __syncthreads();
        int w = t >> 5, lane = t & 31;
        #pragma unroll
        for (int r = 0; r < 4; r++) {
            int row = w * 4 + r;
            float v[8];
            #pragma unroll
            for (int j = 0; j < 8; j++) v[j] = ss[row * 257 + lane + j * 32];
            float m = v[0];
            #pragma unroll
            for (int j = 1; j < 8; j++) m = fmaxf(m, v[j]);
            #pragma unroll
            for (int o = 16; o; o >>= 1) m = fmaxf(m, __shfl_xor_sync(~0u, m, o));
            float p[8], l = 0.f;
            #pragma unroll
            for (int j = 0; j < 8; j++) { p[j] = __expf(v[j] - m); l += p[j]; }
            #pragma unroll
            for (int o = 16; o; o >>= 1) l += __shfl_xor_sync(~0u, l, o);
            float inv = 1.f / l;
            int q = qbase + row;
            #pragma unroll
            for (int j = 0; j < 8; j++)
                g_probs[((b * 4 + h) * Sz + q) * Sz + lane + j * 32] = p[j] * inv;
        }
    }
}

// ---------------------------------------------------------------------------
// K2: rel split-K (halves). CTA per (q, b, i*2+half); 128 threads (4 warps).
// (unchanged — measured 86us @ 81% DRAM, at roofline)
// ---------------------------------------------------------------------------
__global__ void __launch_bounds__(128, 3) rel_kernel(
        const float* __restrict__ rel0, const float* __restrict__ rel1) {
    int q = blockIdx.x, b = blockIdx.y;
    int i = blockIdx.z >> 1, half = blockIdx.z & 1;
    int hr = 2 + i;
    int kbase = half * 128;
    int t = threadIdx.x, lane = t & 31, w = t >> 5;

    extern __shared__ float sm[];
    float* tile = sm;                 // [128][TST]
    float* uvec = sm + 128 * TST;     // 128
    float* kb   = uvec + 128;         // 128
    float* pc   = kb + 128;           // 128
    float* wm   = pc + 128;           // 4
    float* wl   = wm + 4;             // 4

    const float4* rp4 = (const float4*)(((i == 0) ? rel0 : rel1)
                        + (size_t)(b * Sz + q) * Sz * Hz) + (size_t)kbase * 32;
    uint32_t tileu = (uint32_t)__cvta_generic_to_shared(tile);
    #pragma unroll
    for (int r = 0; r < 32; r++) {
        int row = w * 32 + r;
        uint32_t d = tileu + (uint32_t)(row * TST + lane * 4) * 4;
        CP_ASYNC16(d, rp4 + row * 32 + lane);
    }
    CP_COMMIT();

    uvec[t] = g_u[((b * 2 + i) * Sz + q) * Hz + t];
    kb[t]   = g_sbase[((b * 4 + hr) * Sz + q) * Sz + kbase + t];
    __syncthreads();

    CP_WAIT0();
    __syncwarp();
    float s;
    {
        const float4* row = (const float4*)&tile[t * TST];
        const float4* u4  = (const float4*)uvec;
        float acc = 0.f;
        #pragma unroll
        for (int j = 0; j < 32; j++) {
            float4 r = row[j], u = u4[j];
            acc += r.x * u.x + r.y * u.y + r.z * u.z + r.w * u.w;
        }
        s = acc * SCALE + kb[t];
    }
    float mw = s;
    #pragma unroll
    for (int o = 16; o; o >>= 1) mw = fmaxf(mw, __shfl_xor_sync(~0u, mw, o));
    if (lane == 0) wm[w] = mw;
    __syncthreads();

    float M = fmaxf(fmaxf(wm[0], wm[1]), fmaxf(wm[2], wm[3]));
    float p = __expf(s - M);
    pc[t] = p;
    float lw = p;
    #pragma unroll
    for (int o = 16; o; o >>= 1) lw += __shfl_xor_sync(~0u, lw, o);
    if (lane == 0) wl[w] = lw;
    __syncthreads();
    float L = wl[0] + wl[1] + wl[2] + wl[3];

    g_probs[((b * 4 + hr) * Sz + q) * Sz + kbase + t] = p;
    if (t == 0) {
        int mi = ((b * 2 + i) * Sz + q) * 2 + half;
        g_mred[mi * 2 + 0] = M;
        g_mred[mi * 2 + 1] = L;
    }

    {
        float wacc = 0.f;
        #pragma unroll 8
        for (int k = 0; k < 128; k++)
            wacc += pc[k] * tile[k * TST + t];
        g_wpart[(((b * 2 + i) * Sz + q) * 2 + half) * Hz + t] = wacc;
    }
}

// ---------------------------------------------------------------------------
// K2b: combine (rel only). CTA per (q, b, i); 128 threads.
// ---------------------------------------------------------------------------
__global__ void __launch_bounds__(128) combine_kernel(
        const float* __restrict__ Wv, const float* __restrict__ bv) {
    int q = blockIdx.x, b = blockIdx.y, i = blockIdx.z;
    int hr = 2 + i;
    int t = threadIdx.x;

    __shared__ float wfin[Hz];
    __shared__ float wp2[Hz];

    int mi = ((b * 2 + i) * Sz + q) * 2;
    float m0 = g_mred[(mi + 0) * 2 + 0], l0 = g_mred[(mi + 0) * 2 + 1];
    float m1 = g_mred[(mi + 1) * 2 + 0], l1 = g_mred[(mi + 1) * 2 + 1];
    float M = fmaxf(m0, m1);
    float c0 = __expf(m0 - M), c1 = __expf(m1 - M);
    float invL = 1.f / (l0 * c0 + l1 * c1);

    wfin[t] = g_wpart[(mi + 0) * Hz + t] * c0 + g_wpart[(mi + 1) * Hz + t] * c1;

    if (t == 0) {
        g_pscale[((b * 4 + hr) * Sz + q) * 2 + 0] = c0 * invL;
        g_pscale[((b * 4 + hr) * Sz + q) * 2 + 1] = c1 * invL;
    }
    __syncthreads();

    {
        int c = t & 31, g = t >> 5;
        float pp = 0.f;
        #pragma unroll
        for (int j = 0; j < 32; j++)
            pp += wfin[g * 32 + j] * Wv[(g * 32 + j) * Hz + hr * HDz + c];
        wp2[t] = pp;
    }
    __syncthreads();
    if (t < HDz) {
        float ww = wp2[t] + wp2[t + 32] + wp2[t + 64] + wp2[t + 96];
        g_ctxbase[(b * Sz + q) * Hz + hr * HDz + t] = ww * invL + bv[hr * HDz + t];
    }
}

// ---------------------------------------------------------------------------
// K3: ctx = [ctxbase +] probs(scaled) @ Veff. grid (16,8,4), 256 thr, 16 q/CTA.
// ---------------------------------------------------------------------------
__global__ void __launch_bounds__(256) ctxv_kernel() {
    int qt = blockIdx.x, b = blockIdx.y, h = blockIdx.z;
    int qbase = qt * 16;
    int t = threadIdx.x;
    extern __shared__ float sm3[];
    float* Vs  = sm3;                        // 256*33
    float* Ps  = sm3 + 256 * 33;             // 16*256
    float* psc = sm3 + 256 * 33 + 16 * 256;  // 32

    if (h >= 2 && t < 32)
        psc[t] = g_pscale[((b * 4 + h) * Sz + qbase + (t >> 1)) * 2 + (t & 1)];
    #pragma unroll
    for (int jj = 0; jj < 8; jj++) {
        int idx = jj * 256 + t;
        int row = idx >> 3, c4 = idx & 7;
        float4 v = *(const float4*)&g_Veff[(b * Sz + row) * Hz + h * HDz + c4 * 4];
        Vs[row * 33 + c4 * 4 + 0] = v.x;
        Vs[row * 33 + c4 * 4 + 1] = v.y;
        Vs[row * 33 + c4 * 4 + 2] = v.z;
        Vs[row * 33 + c4 * 4 + 3] = v.w;
    }
    __syncthreads();
    #pragma unroll
    for (int jj = 0; jj < 4; jj++) {
        int idx = jj * 256 + t;                  // 1024 float4
        int qq = idx >> 6, k4 = idx & 63;
        float4 v = *(const float4*)&g_probs[((b * 4 + h) * Sz + qbase + qq) * Sz + k4 * 4];
        if (h >= 2) {
            float sc = psc[qq * 2 + (k4 >= 32 ? 1 : 0)];
            v.x *= sc; v.y *= sc; v.z *= sc; v.w *= sc;
        }
        *(float4*)&Ps[qq * 256 + k4 * 4] = v;
    }
    __syncthreads();

    int c = t & 31, g = t >> 5;                  // 8 groups x 2 q each
    const float4* Ps4 = (const float4*)Ps;
    float acc0 = 0.f, acc1 = 0.f;
    #pragma unroll 4
    for (int k4 = 0; k4 < 64; k4++) {
        float v0 = Vs[(k4 * 4 + 0) * 33 + c];
        float v1 = Vs[(k4 * 4 + 1) * 33 + c];
        float v2 = Vs[(k4 * 4 + 2) * 33 + c];
        float v3 = Vs[(k4 * 4 + 3) * 33 + c];
        float4 P0 = Ps4[(g * 2 + 0) * 64 + k4];
        float4 P1 = Ps4[(g * 2 + 1) * 64 + k4];
        acc0 += P0.x * v0 + P0.y * v1 + P0.z * v2 + P0.w * v3;
        acc1 += P1.x * v0 + P1.y * v1 + P1.z * v2 + P1.w * v3;
    }
    #pragma unroll
    for (int r = 0; r < 2; r++) {
        int q = qbase + g * 2 + r;
        float a = (r == 0) ? acc0 : acc1;
        float base = (h >= 2) ? g_ctxbase[(b * Sz + q) * Hz + h * HDz + c] : 0.f;
        g_ctx[(b * Sz + q) * Hz + h * HDz + c] = base + a;
    }
}

// ---------------------------------------------------------------------------
// K4: out = ctx @ Wo + bo. Wo staged in smem; 16 rows/CTA, 256 threads.
// ---------------------------------------------------------------------------
__global__ void __launch_bounds__(256) out_kernel(const float* __restrict__ Wo,
                                                  const float* __restrict__ bo,
                                                  float* __restrict__ out) {
    int r0 = blockIdx.x * 16;
    int t = threadIdx.x;
    extern __shared__ float sm4[];
    float* ws = sm4;                 // 128*128
    float* xs = sm4 + Hz * Hz;       // 16*128

    #pragma unroll
    for (int jj = 0; jj < 16; jj++) {
        int idx = jj * 256 + t;
        *(float4*)&ws[idx * 4] = *(const float4*)&Wo[idx * 4];
    }
    #pragma unroll
    for (int jj = 0; jj < 2; jj++) {
        int idx = jj * 256 + t;
        *(float4*)&xs[idx * 4] = *(const float4*)&g_ctx[r0 * Hz + idx * 4];
    }
    __syncthreads();

    int j = t & 127, rbase = (t >> 7) * 8;
    float a[8];
    float bj = bo[j];
    #pragma unroll
    for (int r = 0; r < 8; r++) a[r] = bj;
    #pragma unroll 4
    for (int i = 0; i < Hz; i++) {
        float w = ws[i * Hz + j];
        #pragma unroll
        for (int r = 0; r < 8; r++)
            a[r] += xs[(rbase + r) * Hz + i] * w;
    }
    #pragma unroll
    for (int r = 0; r < 8; r++)
        out[(r0 + rbase + r) * Hz + j] = a[r];
}

// ---------------------------------------------------------------------------
extern "C" void kernel_launch(void* const* d_in, const int* in_sizes, int n_in,
                              void* d_out, int out_size) {
    const float* X    = (const float*)d_in[0];
    const float* mask = (const float*)d_in[1];
    const float* abs0 = (const float*)d_in[2];
    const float* abs1 = (const float*)d_in[3];
    const float* rel0 = (const float*)d_in[4];
    const float* rel1 = (const float*)d_in[5];
    const float* Wq   = (const float*)d_in[6];
    const float* bq   = (const float*)d_in[7];
    const float* Wk   = (const float*)d_in[8];
    const float* bk   = (const float*)d_in[9];
    const float* Wv   = (const float*)d_in[10];
    const float* bv   = (const float*)d_in[11];
    const float* Wo   = (const float*)d_in[12];
    const float* bo   = (const float*)d_in[13];
    float* out = (float*)d_out;

    size_t prsm  = (size_t)(3 * 16 * XPAD + 3 * 32 * Hz) * sizeof(float);
    size_t sbsm  = (size_t)(32 * 32 + 256 * 33 + 32 * 257) * sizeof(float);
    size_t relsm = (size_t)(128 * TST + 128 + 128 + 128 + 4 + 4) * sizeof(float);
    size_t ctxsm = (size_t)(256 * 33 + 16 * 256 + 32) * sizeof(float);
    size_t outsm = (size_t)(Hz * Hz + 16 * Hz) * sizeof(float);
    cudaFuncSetAttribute(proj_kernel,  cudaFuncAttributeMaxDynamicSharedMemorySize, (int)prsm);
    cudaFuncSetAttribute(sbase_kernel, cudaFuncAttributeMaxDynamicSharedMemorySize, (int)sbsm);
    cudaFuncSetAttribute(rel_kernel,   cudaFuncAttributeMaxDynamicSharedMemorySize, (int)relsm);
    cudaFuncSetAttribute(ctxv_kernel,  cudaFuncAttributeMaxDynamicSharedMemorySize, (int)ctxsm);
    cudaFuncSetAttribute(out_kernel,   cudaFuncAttributeMaxDynamicSharedMemorySize, (int)outsm);

    proj_kernel<<<BSz / 16, 256, prsm>>>(X, abs0, abs1, Wq, bq, Wk, bk, Wv, bv);
    dim3 gs(8, Bz, 4);
    sbase_kernel<<<gs, 256, sbsm>>>(mask, Wk);
    dim3 gr(Sz, Bz, 4);                        // z = i*2 + half
    rel_kernel<<<gr, 128, relsm>>>(rel0, rel1);
    dim3 gc(Sz, Bz, 2);
    combine_kernel<<<gc, 128>>>(Wv, bv);
    dim3 gv(16, Bz, 4);
    ctxv_kernel<<<gv, 256, ctxsm>>>();
    out_kernel<<<BSz / 16, 256, outsm>>>(Wo, bo, out);
}